// round 4
// baseline (speedup 1.0000x reference)
#include <cuda_runtime.h>
#include <cuda_bf16.h>
#include <cstdint>

#define M_TOTAL 8192
#define KDIM    128
#define INVT    5.0f

// ---- device globals (no allocation allowed) -------------------------------
__device__ __align__(16) __nv_bfloat16 hiG[M_TOTAL * KDIM];
__device__ float    dG[M_TOTAL];
__device__ float    accG[M_TOTAL];
__device__ unsigned mG[M_TOTAL];
__device__ int      labG[M_TOTAL];

// ---- helpers --------------------------------------------------------------
__device__ __forceinline__ uint32_t smem_to_u32(const void* p) {
    uint32_t a;
    asm("{ .reg .u64 t; cvta.to.shared.u64 t, %1; cvt.u32.u64 %0, t; }" : "=r"(a) : "l"(p));
    return a;
}
__device__ __forceinline__ void cpa16(uint32_t dst, const void* src) {
    asm volatile("cp.async.cg.shared.global [%0], [%1], 16;" :: "r"(dst), "l"(src) : "memory");
}
__device__ __forceinline__ void ldsm4(uint32_t* r, uint32_t addr) {
    asm volatile("ldmatrix.sync.aligned.m8n8.x4.shared.b16 {%0,%1,%2,%3}, [%4];"
                 : "=r"(r[0]), "=r"(r[1]), "=r"(r[2]), "=r"(r[3]) : "r"(addr));
}
__device__ __forceinline__ void mma16816(float* c, const uint32_t* a, uint32_t b0, uint32_t b1) {
    asm volatile("mma.sync.aligned.m16n8k16.row.col.f32.bf16.bf16.f32 "
                 "{%0,%1,%2,%3}, {%4,%5,%6,%7}, {%8,%9}, {%0,%1,%2,%3};"
                 : "+f"(c[0]), "+f"(c[1]), "+f"(c[2]), "+f"(c[3])
                 : "r"(a[0]), "r"(a[1]), "r"(a[2]), "r"(a[3]), "r"(b0), "r"(b1));
}
// order-preserving float <-> unsigned (for atomicMax)
__device__ __forceinline__ unsigned fenc(float f) {
    unsigned u = __float_as_uint(f);
    return (u >> 31) ? ~u : (u | 0x80000000u);
}
__device__ __forceinline__ float fdec(unsigned e) {
    return (e >> 31) ? __uint_as_float(e & 0x7fffffffu) : __uint_as_float(~e);
}

// ---- kernel 1: bf16 cast, per-row norms, init (4 rows/warp, MLP=4) -------
__global__ void __launch_bounds__(256)
prep_kernel(const float* __restrict__ feat, const long long* __restrict__ labels) {
    const int warp = threadIdx.x >> 5, lane = threadIdx.x & 31;
    const int row = blockIdx.x * 32 + warp * 4 + (lane >> 3);
    const int kc  = (lane & 7) * 16;          // 16 floats per thread
    const float4* src = reinterpret_cast<const float4*>(feat + (size_t)row * KDIM + kc);
    float4 v[4];
    #pragma unroll
    for (int j = 0; j < 4; j++) v[j] = src[j];

    float ss = 0.f;
    uint32_t pk[8];
    #pragma unroll
    for (int j = 0; j < 4; j++) {
        float x0 = v[j].x, x1 = v[j].y, x2 = v[j].z, x3 = v[j].w;
        ss += x0 * x0 + x1 * x1 + x2 * x2 + x3 * x3;
        __nv_bfloat162 p0 = __floats2bfloat162_rn(x0, x1);
        __nv_bfloat162 p1 = __floats2bfloat162_rn(x2, x3);
        pk[j * 2]     = *reinterpret_cast<uint32_t*>(&p0);
        pk[j * 2 + 1] = *reinterpret_cast<uint32_t*>(&p1);
    }
    uint4* dst = reinterpret_cast<uint4*>(hiG + (size_t)row * KDIM + kc);
    dst[0] = make_uint4(pk[0], pk[1], pk[2], pk[3]);
    dst[1] = make_uint4(pk[4], pk[5], pk[6], pk[7]);

    #pragma unroll
    for (int o = 4; o; o >>= 1) ss += __shfl_xor_sync(0xffffffffu, ss, o);
    if ((lane & 7) == 0) {
        dG[row]   = ss * INVT;
        accG[row] = 0.0f;
        mG[row]   = 0u;
        labG[row] = (int)labels[row];
    }
}

// ---- kernel 2: symmetric bf16 HMMA GEMM + dual-sided epilogue ------------
// Only tiles tj >= ti computed. 128x128 tile, 8 warps (4x2), 32x64 each.

#define SMEM_A   0
#define SMEM_B   32768
#define SMEM_LAB 65536
#define SMEM_DC  66048
#define SMEM_SZ  66560

__global__ void __launch_bounds__(256, 2)
main_kernel() {
    const int ti = blockIdx.y, tj = blockIdx.x;
    if (tj < ti) return;
    const bool diag = (ti == tj);

    extern __shared__ char smem[];
    const uint32_t sb = smem_to_u32(smem);
    const int t = threadIdx.x;
    const int lane = t & 31, wid = t >> 5;
    const int rowbase = ti * 128;
    const int colbase = tj * 128;

    // ---- load A (rows) and B (cols) tiles, swizzled ----
    {
        const int q = t & 15, r0 = t >> 4;
        const __nv_bfloat16* Ag = hiG + (size_t)(rowbase + r0) * KDIM + q * 8;
        const __nv_bfloat16* Bg = hiG + (size_t)(colbase + r0) * KDIM + q * 8;
        #pragma unroll
        for (int j = 0; j < 8; j++) {
            int row = r0 + j * 16;
            uint32_t sw = (uint32_t)((q ^ (row & 7)) * 16);
            cpa16(sb + SMEM_A + row * 256 + sw, Ag + (size_t)j * 16 * KDIM);
            cpa16(sb + SMEM_B + row * 256 + sw, Bg + (size_t)j * 16 * KDIM);
        }
    }
    if (t < 128) {
        reinterpret_cast<int*>(smem + SMEM_LAB)[t]   = labG[colbase + t];
        reinterpret_cast<float*>(smem + SMEM_DC)[t]  = dG[colbase + t];
    }
    asm volatile("cp.async.commit_group;" ::: "memory");
    asm volatile("cp.async.wait_group 0;" ::: "memory");
    __syncthreads();

    // ---- GEMM ----
    const int wm = wid & 3, wn = wid >> 2;
    float acc[2][8][4];
    #pragma unroll
    for (int mi = 0; mi < 2; mi++)
        #pragma unroll
        for (int bi = 0; bi < 8; bi++)
            #pragma unroll
            for (int rg = 0; rg < 4; rg++) acc[mi][bi][rg] = 0.f;

    #pragma unroll
    for (int ks = 0; ks < 8; ks++) {
        uint32_t af[2][4];
        #pragma unroll
        for (int mi = 0; mi < 2; mi++) {
            int row = wm * 32 + mi * 16 + (lane & 15);
            int ql  = ks * 2 + (lane >> 4);
            ldsm4(af[mi], sb + SMEM_A + row * 256 + ((ql ^ (row & 7)) * 16));
        }
        uint32_t bfm[4][4];
        #pragma unroll
        for (int bi = 0; bi < 4; bi++) {
            int row = wn * 64 + bi * 16 + (lane & 15);
            int ql  = ks * 2 + (lane >> 4);
            ldsm4(bfm[bi], sb + SMEM_B + row * 256 + ((ql ^ (row & 7)) * 16));
        }
        #pragma unroll
        for (int mi = 0; mi < 2; mi++)
            #pragma unroll
            for (int bi = 0; bi < 4; bi++) {
                mma16816(acc[mi][bi * 2 + 0], af[mi], bfm[bi][0], bfm[bi][2]);
                mma16816(acc[mi][bi * 2 + 1], af[mi], bfm[bi][1], bfm[bi][3]);
            }
    }

    // ---- epilogue ----
    int grow[4]; float d4[4]; int rl[4]; float mx4[4], ac4[4];
    #pragma unroll
    for (int s = 0; s < 4; s++) {
        int mi = s >> 1, h = s & 1;
        grow[s] = rowbase + wm * 32 + mi * 16 + h * 8 + (lane >> 2);
        d4[s]   = dG[grow[s]];
        rl[s]   = labG[grow[s]];
        mx4[s]  = -1e30f;
        ac4[s]  = 0.f;
    }
    const int*   labC = reinterpret_cast<const int*>(smem + SMEM_LAB);
    const float* dCs  = reinterpret_cast<const float*>(smem + SMEM_DC);

    float mxC[16], acC[16];
    #pragma unroll
    for (int ci = 0; ci < 16; ci++) { mxC[ci] = -1e30f; acC[ci] = 0.f; }

    #pragma unroll
    for (int mi = 0; mi < 2; mi++)
        #pragma unroll
        for (int bi = 0; bi < 8; bi++)
            #pragma unroll
            for (int rg = 0; rg < 4; rg++) {
                int s = mi * 2 + (rg >> 1);
                int cl = wn * 64 + bi * 8 + (lane & 3) * 2 + (rg & 1);
                float sim = acc[mi][bi][rg] * INVT;
                bool same = (rl[s] == labC[cl]);
                // row side
                mx4[s] = fmaxf(mx4[s], sim);
                float tt = sim - d4[s];
                if (__builtin_expect(tt > -75.f, 0)) {
                    if (!diag || (colbase + cl) != grow[s]) {
                        float e = __expf(tt);
                        ac4[s] += same ? e : -e;
                    }
                }
                // col side (transposed contribution), off-diagonal tiles only
                if (!diag) {
                    int ci = bi * 2 + (rg & 1);
                    mxC[ci] = fmaxf(mxC[ci], sim);
                    float t2 = sim - dCs[cl];
                    if (__builtin_expect(t2 > -75.f, 0)) {
                        float e2 = __expf(t2);
                        acC[ci] += same ? e2 : -e2;
                    }
                }
            }

    #pragma unroll
    for (int s = 0; s < 4; s++) {
        float a = ac4[s], m = mx4[s];
        a += __shfl_xor_sync(0xffffffffu, a, 1);
        a += __shfl_xor_sync(0xffffffffu, a, 2);
        m = fmaxf(m, __shfl_xor_sync(0xffffffffu, m, 1));
        m = fmaxf(m, __shfl_xor_sync(0xffffffffu, m, 2));
        if ((lane & 3) == 0) {
            atomicAdd(&accG[grow[s]], a);
            atomicMax(&mG[grow[s]], fenc(m));
        }
    }
    if (!diag) {
        #pragma unroll
        for (int ci = 0; ci < 16; ci++) {
            float a = acC[ci], m = mxC[ci];
            #pragma unroll
            for (int o = 4; o <= 16; o <<= 1) {
                a += __shfl_xor_sync(0xffffffffu, a, o);
                m = fmaxf(m, __shfl_xor_sync(0xffffffffu, m, o));
            }
            if (lane < 4) {
                int col = colbase + wn * 64 + (ci >> 1) * 8 + lane * 2 + (ci & 1);
                atomicAdd(&accG[col], a);
                atomicMax(&mG[col], fenc(m));
            }
        }
    }
}

// ---- kernel 3: exact max rebase + mean -----------------------------------
__global__ void final_kernel(float* __restrict__ out) {
    __shared__ double red[32];
    const int t = threadIdx.x, lane = t & 31, warp = t >> 5;
    double s = 0.0;
    #pragma unroll
    for (int i = 0; i < 8; i++) {
        int r = t + i * 1024;
        float m = fdec(mG[r]);
        s += (double)(accG[r] * __expf(dG[r] - m));
    }
    #pragma unroll
    for (int o = 16; o; o >>= 1) s += __shfl_xor_sync(0xffffffffu, s, o);
    if (lane == 0) red[warp] = s;
    __syncthreads();
    if (warp == 0) {
        double v = red[lane];
        #pragma unroll
        for (int o = 16; o; o >>= 1) v += __shfl_xor_sync(0xffffffffu, v, o);
        if (lane == 0) out[0] = (float)(-v / (double)M_TOTAL);
    }
}

// ---- host ----------------------------------------------------------------
extern "C" void kernel_launch(void* const* d_in, const int* in_sizes, int n_in,
                              void* d_out, int out_size) {
    const float*     feat   = (const float*)d_in[0];
    const long long* labels = (const long long*)d_in[1];
    float* out = (float*)d_out;

    cudaFuncSetAttribute(main_kernel, cudaFuncAttributeMaxDynamicSharedMemorySize, SMEM_SZ);

    prep_kernel<<<M_TOTAL / 32, 256>>>(feat, labels);
    main_kernel<<<dim3(64, 64), 256, SMEM_SZ>>>();
    final_kernel<<<1, 1024>>>(out);
}

// round 5
// speedup vs baseline: 1.2819x; 1.2819x over previous
#include <cuda_runtime.h>
#include <cuda_bf16.h>
#include <cstdint>

#define M_TOTAL 8192
#define KDIM    128
#define INVT    5.0f

// ---- device globals (no allocation allowed) -------------------------------
__device__ __align__(16) __nv_bfloat16 hiG[M_TOTAL * KDIM];
__device__ float    dG[M_TOTAL];
__device__ float    accG[M_TOTAL];
__device__ unsigned mG[M_TOTAL];
__device__ int      labG[M_TOTAL];

// ---- helpers --------------------------------------------------------------
__device__ __forceinline__ uint32_t smem_to_u32(const void* p) {
    uint32_t a;
    asm("{ .reg .u64 t; cvta.to.shared.u64 t, %1; cvt.u32.u64 %0, t; }" : "=r"(a) : "l"(p));
    return a;
}
__device__ __forceinline__ void cpa16(uint32_t dst, const void* src) {
    asm volatile("cp.async.cg.shared.global [%0], [%1], 16;" :: "r"(dst), "l"(src) : "memory");
}
__device__ __forceinline__ void ldsm4(uint32_t* r, uint32_t addr) {
    asm volatile("ldmatrix.sync.aligned.m8n8.x4.shared.b16 {%0,%1,%2,%3}, [%4];"
                 : "=r"(r[0]), "=r"(r[1]), "=r"(r[2]), "=r"(r[3]) : "r"(addr));
}
__device__ __forceinline__ void mma16816(float* c, const uint32_t* a, uint32_t b0, uint32_t b1) {
    asm volatile("mma.sync.aligned.m16n8k16.row.col.f32.bf16.bf16.f32 "
                 "{%0,%1,%2,%3}, {%4,%5,%6,%7}, {%8,%9}, {%0,%1,%2,%3};"
                 : "+f"(c[0]), "+f"(c[1]), "+f"(c[2]), "+f"(c[3])
                 : "r"(a[0]), "r"(a[1]), "r"(a[2]), "r"(a[3]), "r"(b0), "r"(b1));
}
// order-preserving float <-> unsigned (for atomicMax)
__device__ __forceinline__ unsigned fenc(float f) {
    unsigned u = __float_as_uint(f);
    return (u >> 31) ? ~u : (u | 0x80000000u);
}
__device__ __forceinline__ float fdec(unsigned e) {
    return (e >> 31) ? __uint_as_float(e & 0x7fffffffu) : __uint_as_float(~e);
}

// ---- kernel 1: bf16 cast, per-row norms, init (16 thr/row, MLP=2) --------
__global__ void __launch_bounds__(256)
prep_kernel(const float* __restrict__ feat, const long long* __restrict__ labels) {
    const int g   = blockIdx.x * 256 + threadIdx.x;
    const int row = g >> 4;
    const int sub = g & 15;               // 8 floats per thread
    const float4* src = reinterpret_cast<const float4*>(feat + (size_t)row * KDIM + sub * 8);
    float4 v0 = src[0], v1 = src[1];

    float ss = v0.x*v0.x + v0.y*v0.y + v0.z*v0.z + v0.w*v0.w
             + v1.x*v1.x + v1.y*v1.y + v1.z*v1.z + v1.w*v1.w;

    __nv_bfloat162 p0 = __floats2bfloat162_rn(v0.x, v0.y);
    __nv_bfloat162 p1 = __floats2bfloat162_rn(v0.z, v0.w);
    __nv_bfloat162 p2 = __floats2bfloat162_rn(v1.x, v1.y);
    __nv_bfloat162 p3 = __floats2bfloat162_rn(v1.z, v1.w);
    *reinterpret_cast<uint4*>(hiG + (size_t)row * KDIM + sub * 8) =
        make_uint4(*reinterpret_cast<uint32_t*>(&p0), *reinterpret_cast<uint32_t*>(&p1),
                   *reinterpret_cast<uint32_t*>(&p2), *reinterpret_cast<uint32_t*>(&p3));

    #pragma unroll
    for (int o = 8; o; o >>= 1) ss += __shfl_xor_sync(0xffffffffu, ss, o);
    if (sub == 0) {
        dG[row]   = ss * INVT;
        accG[row] = 0.0f;
        mG[row]   = 0u;
        labG[row] = (int)labels[row];
    }
}

// ---- kernel 2: symmetric HMMA GEMM; row-side from regs, col-side via smem
// Only tiles tj >= ti. 128x128 tile, 8 warps (4x2), 32x64 micro-tile.

#define SMEM_A   0
#define SMEM_B   32768
#define SMEM_SIM 0              // reuses A+B after GEMM: 128*129*4 = 66048
#define SMEM_LAB 66048          // col labels (512)
#define SMEM_DC  66560          // col dG (512)
#define SMEM_LR  67072          // row labels (512)
#define SMEM_SZ  67584

// sim store swizzle: element (r, c) -> word index r*129 + ((c + 2r) & 127)
__device__ __forceinline__ int sim_idx(int r, int c) {
    return r * 129 + ((c + 2 * r) & 127);
}

__global__ void __launch_bounds__(256, 2)
main_kernel() {
    const int ti = blockIdx.y, tj = blockIdx.x;
    if (tj < ti) return;
    const bool diag = (ti == tj);

    extern __shared__ char smem[];
    const uint32_t sb = smem_to_u32(smem);
    const int t = threadIdx.x;
    const int lane = t & 31, wid = t >> 5;
    const int rowbase = ti * 128;
    const int colbase = tj * 128;

    // ---- load A (rows) and B (cols) tiles, swizzled for ldmatrix ----
    {
        const int q = t & 15, r0 = t >> 4;
        const __nv_bfloat16* Ag = hiG + (size_t)(rowbase + r0) * KDIM + q * 8;
        const __nv_bfloat16* Bg = hiG + (size_t)(colbase + r0) * KDIM + q * 8;
        #pragma unroll
        for (int j = 0; j < 8; j++) {
            int row = r0 + j * 16;
            uint32_t sw = (uint32_t)((q ^ (row & 7)) * 16);
            cpa16(sb + SMEM_A + row * 256 + sw, Ag + (size_t)j * 16 * KDIM);
            cpa16(sb + SMEM_B + row * 256 + sw, Bg + (size_t)j * 16 * KDIM);
        }
    }
    if (t < 128) {
        reinterpret_cast<int*>(smem + SMEM_LAB)[t]  = labG[colbase + t];
        reinterpret_cast<float*>(smem + SMEM_DC)[t] = dG[colbase + t];
        reinterpret_cast<int*>(smem + SMEM_LR)[t]   = labG[rowbase + t];
    }
    asm volatile("cp.async.commit_group;" ::: "memory");
    asm volatile("cp.async.wait_group 0;" ::: "memory");
    __syncthreads();

    // ---- GEMM ----
    const int wm = wid & 3, wn = wid >> 2;
    float acc[2][8][4];
    #pragma unroll
    for (int mi = 0; mi < 2; mi++)
        #pragma unroll
        for (int bi = 0; bi < 8; bi++)
            #pragma unroll
            for (int rg = 0; rg < 4; rg++) acc[mi][bi][rg] = 0.f;

    #pragma unroll
    for (int ks = 0; ks < 8; ks++) {
        uint32_t af[2][4];
        #pragma unroll
        for (int mi = 0; mi < 2; mi++) {
            int row = wm * 32 + mi * 16 + (lane & 15);
            int ql  = ks * 2 + (lane >> 4);
            ldsm4(af[mi], sb + SMEM_A + row * 256 + ((ql ^ (row & 7)) * 16));
        }
        uint32_t bfm[4][4];
        #pragma unroll
        for (int bi = 0; bi < 4; bi++) {
            int row = wn * 64 + bi * 16 + (lane & 15);
            int ql  = ks * 2 + (lane >> 4);
            ldsm4(bfm[bi], sb + SMEM_B + row * 256 + ((ql ^ (row & 7)) * 16));
        }
        #pragma unroll
        for (int mi = 0; mi < 2; mi++)
            #pragma unroll
            for (int bi = 0; bi < 4; bi++) {
                mma16816(acc[mi][bi * 2 + 0], af[mi], bfm[bi][0], bfm[bi][2]);
                mma16816(acc[mi][bi * 2 + 1], af[mi], bfm[bi][1], bfm[bi][3]);
            }
    }

    // ---- row-side epilogue from registers (proven path) ----
    const int* labC = reinterpret_cast<const int*>(smem + SMEM_LAB);
    {
        int grow[4]; float d4[4]; int rl[4]; float mx4[4], ac4[4];
        #pragma unroll
        for (int s = 0; s < 4; s++) {
            int mi = s >> 1, h = s & 1;
            grow[s] = rowbase + wm * 32 + mi * 16 + h * 8 + (lane >> 2);
            d4[s]   = dG[grow[s]];
            rl[s]   = labG[grow[s]];
            mx4[s]  = -1e30f;
            ac4[s]  = 0.f;
        }
        #pragma unroll
        for (int mi = 0; mi < 2; mi++)
            #pragma unroll
            for (int bi = 0; bi < 8; bi++)
                #pragma unroll
                for (int rg = 0; rg < 4; rg++) {
                    int s = mi * 2 + (rg >> 1);
                    float sim = acc[mi][bi][rg] * INVT;
                    mx4[s] = fmaxf(mx4[s], sim);
                    float tt = sim - d4[s];
                    if (__builtin_expect(tt > -75.f, 0)) {
                        int cl = wn * 64 + bi * 8 + (lane & 3) * 2 + (rg & 1);
                        if (!diag || (colbase + cl) != grow[s]) {
                            float e = __expf(tt);
                            ac4[s] += (rl[s] == labC[cl]) ? e : -e;
                        }
                    }
                }
        #pragma unroll
        for (int s = 0; s < 4; s++) {
            float a = ac4[s], m = mx4[s];
            a += __shfl_xor_sync(0xffffffffu, a, 1);
            a += __shfl_xor_sync(0xffffffffu, a, 2);
            m = fmaxf(m, __shfl_xor_sync(0xffffffffu, m, 1));
            m = fmaxf(m, __shfl_xor_sync(0xffffffffu, m, 2));
            if ((lane & 3) == 0) {
                atomicAdd(&accG[grow[s]], a);
                atomicMax(&mG[grow[s]], fenc(m));
            }
        }
    }

    // ---- col-side via smem sim tile (off-diagonal tiles only) ----
    if (!diag) {
        __syncthreads();   // A/B reads done everywhere; safe to overwrite
        float* simS = reinterpret_cast<float*>(smem + SMEM_SIM);
        #pragma unroll
        for (int mi = 0; mi < 2; mi++)
            #pragma unroll
            for (int bi = 0; bi < 8; bi++)
                #pragma unroll
                for (int rg = 0; rg < 4; rg++) {
                    int r = wm * 32 + mi * 16 + (rg >> 1) * 8 + (lane >> 2);
                    int c = wn * 64 + bi * 8 + (lane & 3) * 2 + (rg & 1);
                    simS[sim_idx(r, c)] = acc[mi][bi][rg];
                }
        __syncthreads();

        const int   c    = t & 127;
        const int   r0   = (t >> 7) * 64;
        const float dcol = reinterpret_cast<const float*>(smem + SMEM_DC)[c];
        const int   lc   = labC[c];
        const int*  labR = reinterpret_cast<const int*>(smem + SMEM_LR);
        float mx = -1e30f, ac = 0.f;
        #pragma unroll 8
        for (int r = r0; r < r0 + 64; r++) {
            float sim = simS[sim_idx(r, c)] * INVT;
            mx = fmaxf(mx, sim);
            float tt = sim - dcol;
            if (__builtin_expect(tt > -75.f, 0)) {
                float e = __expf(tt);
                ac += (labR[r] == lc) ? e : -e;
            }
        }
        atomicAdd(&accG[colbase + c], ac);
        atomicMax(&mG[colbase + c], fenc(mx));
    }
}

// ---- kernel 3: exact max rebase + mean -----------------------------------
__global__ void final_kernel(float* __restrict__ out) {
    __shared__ double red[32];
    const int t = threadIdx.x, lane = t & 31, warp = t >> 5;
    double s = 0.0;
    #pragma unroll
    for (int i = 0; i < 8; i++) {
        int r = t + i * 1024;
        float m = fdec(mG[r]);
        s += (double)(accG[r] * __expf(dG[r] - m));
    }
    #pragma unroll
    for (int o = 16; o; o >>= 1) s += __shfl_xor_sync(0xffffffffu, s, o);
    if (lane == 0) red[warp] = s;
    __syncthreads();
    if (warp == 0) {
        double v = red[lane];
        #pragma unroll
        for (int o = 16; o; o >>= 1) v += __shfl_xor_sync(0xffffffffu, v, o);
        if (lane == 0) out[0] = (float)(-v / (double)M_TOTAL);
    }
}

// ---- host ----------------------------------------------------------------
extern "C" void kernel_launch(void* const* d_in, const int* in_sizes, int n_in,
                              void* d_out, int out_size) {
    const float*     feat   = (const float*)d_in[0];
    const long long* labels = (const long long*)d_in[1];
    float* out = (float*)d_out;

    cudaFuncSetAttribute(main_kernel, cudaFuncAttributeMaxDynamicSharedMemorySize, SMEM_SZ);

    prep_kernel<<<M_TOTAL * 16 / 256, 256>>>(feat, labels);
    main_kernel<<<dim3(64, 64), 256, SMEM_SZ>>>();
    final_kernel<<<1, 1024>>>(out);
}